// round 1
// baseline (speedup 1.0000x reference)
#include <cuda_runtime.h>

// EGNN forward, N=50000 nodes, E=1.6M edges, H=32, DX=16, L=2.
// Pipeline per graph replay:
//   init      : x = pos@projW^T, h = attrs@embW^T+b, A/B = h@W1(l=0) split, zero aggs+cnt
//   count     : cnt[row] += 1 per edge
//   layer l   : edge_kernel  (fused edge MLPs + coord head, vector red scatters)
//               node_kernel  (x += tagg/cnt, h += node MLP, next-layer A/B, final out)
// All state in __device__ globals (no allocation).

#define H   32
#define DX  16
#define NMAX 50048

__device__ __align__(16) float g_x[NMAX * DX];
__device__ __align__(16) float g_h[NMAX * H];
__device__ __align__(16) float g_A[NMAX * H];
__device__ __align__(16) float g_B[NMAX * H];
__device__ __align__(16) float g_magg[NMAX * H];
__device__ __align__(16) float g_tagg[NMAX * DX];
__device__ float g_cnt[NMAX];

__device__ __forceinline__ float silu_f(float v) {
    return v * (1.0f / (1.0f + __expf(-v)));
}

// Vectorized global reduction (sm_90+): 4 floats per RED instruction.
__device__ __forceinline__ void red_add_v4(float* addr, float a, float b, float c, float d) {
    asm volatile("red.global.add.v4.f32 [%0], {%1,%2,%3,%4};"
                 :: "l"(addr), "f"(a), "f"(b), "f"(c), "f"(d)
                 : "memory");
}

// ---------------------------------------------------------------------------
// init: x0, h0, A0/B0, zero aggregators and counts
// ---------------------------------------------------------------------------
__global__ __launch_bounds__(128) void init_kernel(
    const float* __restrict__ attrs,  // [N,3]
    const float* __restrict__ pos,    // [N,3]
    const float* __restrict__ projW,  // [16,3]
    const float* __restrict__ embW,   // [32,3]
    const float* __restrict__ embB,   // [32]
    const float* __restrict__ eW1,    // layer0 edge_W1 [32][68]
    const float* __restrict__ eb1,    // layer0 edge_b1 [32]
    int n)
{
    __shared__ float sWa[H][H];
    __shared__ float sWb[H][H];
    for (int idx = threadIdx.x; idx < H * H; idx += 128) {
        int j = idx >> 5, k = idx & 31;
        sWa[j][k] = eW1[j * 68 + k];
        sWb[j][k] = eW1[j * 68 + 32 + k];
    }
    __syncthreads();

    int i = blockIdx.x * 128 + threadIdx.x;
    if (i >= n) return;

    float p0 = pos[i * 3 + 0], p1 = pos[i * 3 + 1], p2 = pos[i * 3 + 2];
    float xv[DX];
#pragma unroll
    for (int j = 0; j < DX; j++)
        xv[j] = projW[j * 3 + 0] * p0 + projW[j * 3 + 1] * p1 + projW[j * 3 + 2] * p2;

    float4* xo = (float4*)&g_x[i * DX];
#pragma unroll
    for (int q = 0; q < 4; q++)
        xo[q] = make_float4(xv[4 * q], xv[4 * q + 1], xv[4 * q + 2], xv[4 * q + 3]);

    float a0 = attrs[i * 3 + 0], a1 = attrs[i * 3 + 1], a2 = attrs[i * 3 + 2];
    float hv[H];
#pragma unroll
    for (int j = 0; j < H; j++)
        hv[j] = embW[j * 3 + 0] * a0 + embW[j * 3 + 1] * a1 + embW[j * 3 + 2] * a2 + embB[j];

    float4* ho = (float4*)&g_h[i * H];
#pragma unroll
    for (int q = 0; q < 8; q++)
        ho[q] = make_float4(hv[4 * q], hv[4 * q + 1], hv[4 * q + 2], hv[4 * q + 3]);

    float Av[H], Bv[H];
#pragma unroll
    for (int j = 0; j < H; j++) {
        float accA = eb1[j];
        float accB = 0.0f;
#pragma unroll
        for (int k = 0; k < H; k++) {
            accA += sWa[j][k] * hv[k];
            accB += sWb[j][k] * hv[k];
        }
        Av[j] = accA;
        Bv[j] = accB;
    }
    float4* Ao = (float4*)&g_A[i * H];
    float4* Bo = (float4*)&g_B[i * H];
#pragma unroll
    for (int q = 0; q < 8; q++) {
        Ao[q] = make_float4(Av[4 * q], Av[4 * q + 1], Av[4 * q + 2], Av[4 * q + 3]);
        Bo[q] = make_float4(Bv[4 * q], Bv[4 * q + 1], Bv[4 * q + 2], Bv[4 * q + 3]);
    }

    const float4 z4 = make_float4(0.f, 0.f, 0.f, 0.f);
    float4* mz = (float4*)&g_magg[i * H];
    float4* tz = (float4*)&g_tagg[i * DX];
#pragma unroll
    for (int q = 0; q < 8; q++) mz[q] = z4;
#pragma unroll
    for (int q = 0; q < 4; q++) tz[q] = z4;
    g_cnt[i] = 0.0f;
}

// ---------------------------------------------------------------------------
// count: out-degree of row
// ---------------------------------------------------------------------------
__global__ void count_kernel(const int* __restrict__ ei, int E)
{
    int e = blockIdx.x * blockDim.x + threadIdx.x;
    if (e < E) atomicAdd(&g_cnt[ei[e]], 1.0f);
}

// ---------------------------------------------------------------------------
// edge kernel: fused edge MLPs + coord head, scatter via vector red
// ---------------------------------------------------------------------------
#define ETPB 128

__global__ __launch_bounds__(ETPB) void edge_kernel(
    const int* __restrict__ ei, int E,
    const float* __restrict__ pos,
    const float* __restrict__ W1,   // [32][68] this layer (only cols 64..67 used here)
    const float* __restrict__ W2,   // [32][32]
    const float* __restrict__ b2,   // [32]
    const float* __restrict__ cW1,  // [32][32]
    const float* __restrict__ cb1,  // [32]
    const float* __restrict__ cW2)  // [32]
{
    __shared__ float s_wr[H];
    __shared__ float s_we[3][H];
    __shared__ float s_W2t[H][H];   // [k][j]
    __shared__ float s_b2[H];
    __shared__ float s_cW1t[H][H];  // [k][j]
    __shared__ float s_cb1[H];
    __shared__ float s_cw2[H];

    for (int idx = threadIdx.x; idx < H * H; idx += ETPB) {
        int j = idx >> 5, k = idx & 31;
        s_W2t[k][j]  = W2[idx];
        s_cW1t[k][j] = cW1[idx];
    }
    if (threadIdx.x < H) {
        int j = threadIdx.x;
        s_wr[j]    = W1[j * 68 + 64];
        s_we[0][j] = W1[j * 68 + 65];
        s_we[1][j] = W1[j * 68 + 66];
        s_we[2][j] = W1[j * 68 + 67];
        s_b2[j]  = b2[j];
        s_cb1[j] = cb1[j];
        s_cw2[j] = cW2[j];
    }
    __syncthreads();

    int e = blockIdx.x * ETPB + threadIdx.x;
    if (e >= E) return;

    int row = ei[e];
    int col = ei[E + e];

    float ea0 = pos[row * 3 + 0] - pos[col * 3 + 0];
    float ea1 = pos[row * 3 + 1] - pos[col * 3 + 1];
    float ea2 = pos[row * 3 + 2] - pos[col * 3 + 2];

    float cd[DX];
    const float4* xr = (const float4*)&g_x[row * DX];
    const float4* xc = (const float4*)&g_x[col * DX];
    float radial = 0.0f;
#pragma unroll
    for (int q = 0; q < 4; q++) {
        float4 a = xr[q], b = xc[q];
        float d0 = a.x - b.x, d1 = a.y - b.y, d2 = a.z - b.z, d3 = a.w - b.w;
        cd[4 * q + 0] = d0; cd[4 * q + 1] = d1; cd[4 * q + 2] = d2; cd[4 * q + 3] = d3;
        radial += d0 * d0 + d1 * d1 + d2 * d2 + d3 * d3;
    }

    // edge MLP layer 1 (A/B-factored) -> m1 (reuse acc), layer 2 -> m
    float m[H];
    {
        const float4* Ar = (const float4*)&g_A[row * H];
        const float4* Bc = (const float4*)&g_B[col * H];
        float acc[H];
#pragma unroll
        for (int q = 0; q < 8; q++) {
            float4 a = Ar[q], b = Bc[q];
            acc[4 * q + 0] = a.x + b.x; acc[4 * q + 1] = a.y + b.y;
            acc[4 * q + 2] = a.z + b.z; acc[4 * q + 3] = a.w + b.w;
        }
#pragma unroll
        for (int j = 0; j < H; j++) {
            acc[j] += s_wr[j] * radial + s_we[0][j] * ea0 + s_we[1][j] * ea1 + s_we[2][j] * ea2;
            acc[j] = silu_f(acc[j]);
        }
        float acc2[H];
#pragma unroll
        for (int j = 0; j < H; j++) acc2[j] = s_b2[j];
#pragma unroll
        for (int k = 0; k < H; k++) {
            float mk = acc[k];
#pragma unroll
            for (int j = 0; j < H; j++) acc2[j] += s_W2t[k][j] * mk;
        }
#pragma unroll
        for (int j = 0; j < H; j++) m[j] = silu_f(acc2[j]);
    }

    // coord head: cm = cW2 . silu(cW1 m + cb1)
    float cm;
    {
        float cacc[H];
#pragma unroll
        for (int j = 0; j < H; j++) cacc[j] = s_cb1[j];
#pragma unroll
        for (int k = 0; k < H; k++) {
            float mk = m[k];
#pragma unroll
            for (int j = 0; j < H; j++) cacc[j] += s_cW1t[k][j] * mk;
        }
        cm = 0.0f;
#pragma unroll
        for (int j = 0; j < H; j++) cm += s_cw2[j] * silu_f(cacc[j]);
    }

    float* mago = &g_magg[row * H];
#pragma unroll
    for (int q = 0; q < 8; q++)
        red_add_v4(mago + 4 * q, m[4 * q], m[4 * q + 1], m[4 * q + 2], m[4 * q + 3]);

    float* tago = &g_tagg[row * DX];
#pragma unroll
    for (int q = 0; q < 4; q++)
        red_add_v4(tago + 4 * q,
                   cd[4 * q] * cm, cd[4 * q + 1] * cm, cd[4 * q + 2] * cm, cd[4 * q + 3] * cm);
}

// ---------------------------------------------------------------------------
// node kernel: x update, node MLP residual, next-layer A/B, final projection
// ---------------------------------------------------------------------------
#define NTPB 128

__global__ __launch_bounds__(NTPB) void node_kernel(
    const float* __restrict__ nW1,   // [32][64]
    const float* __restrict__ nb1,   // [32]
    const float* __restrict__ nW2,   // [32][32]
    const float* __restrict__ nb2,   // [32]
    const float* __restrict__ eW1n,  // next-layer edge_W1 [32][68] or null
    const float* __restrict__ eb1n,  // next-layer edge_b1 [32] or null
    const float* __restrict__ linW,  // [3][16] or null
    float* __restrict__ out,         // [N,3]
    int n)
{
    __shared__ float sN1[H][2 * H];
    __shared__ float sN2[H][H];
    __shared__ float sEA[H][H];
    __shared__ float sEB[H][H];

    for (int idx = threadIdx.x; idx < H * 2 * H; idx += NTPB)
        sN1[idx >> 6][idx & 63] = nW1[idx];
    for (int idx = threadIdx.x; idx < H * H; idx += NTPB) {
        sN2[idx >> 5][idx & 31] = nW2[idx];
        if (eW1n) {
            int j = idx >> 5, k = idx & 31;
            sEA[j][k] = eW1n[j * 68 + k];
            sEB[j][k] = eW1n[j * 68 + 32 + k];
        }
    }
    __syncthreads();

    int i = blockIdx.x * NTPB + threadIdx.x;
    if (i >= n) return;

    float cnt = g_cnt[i];
    float inv = 1.0f / fmaxf(cnt, 1.0f);

    const float4 z4 = make_float4(0.f, 0.f, 0.f, 0.f);

    float xv[DX];
    float4* xp = (float4*)&g_x[i * DX];
    float4* tp = (float4*)&g_tagg[i * DX];
#pragma unroll
    for (int q = 0; q < 4; q++) {
        float4 a = xp[q], t = tp[q];
        xv[4 * q + 0] = a.x + t.x * inv;
        xv[4 * q + 1] = a.y + t.y * inv;
        xv[4 * q + 2] = a.z + t.z * inv;
        xv[4 * q + 3] = a.w + t.w * inv;
        xp[q] = make_float4(xv[4 * q], xv[4 * q + 1], xv[4 * q + 2], xv[4 * q + 3]);
        tp[q] = z4;   // reset for next layer / next replay
    }

    float hv[H], mg[H];
    float4* hp = (float4*)&g_h[i * H];
    float4* mp = (float4*)&g_magg[i * H];
#pragma unroll
    for (int q = 0; q < 8; q++) {
        float4 a = hp[q];
        hv[4 * q + 0] = a.x; hv[4 * q + 1] = a.y; hv[4 * q + 2] = a.z; hv[4 * q + 3] = a.w;
        float4 b = mp[q];
        mg[4 * q + 0] = b.x; mg[4 * q + 1] = b.y; mg[4 * q + 2] = b.z; mg[4 * q + 3] = b.w;
        mp[q] = z4;   // reset
    }

    float u[H];
#pragma unroll
    for (int j = 0; j < H; j++) {
        float acc = nb1[j];
#pragma unroll
        for (int k = 0; k < H; k++) acc += sN1[j][k] * hv[k];
#pragma unroll
        for (int k = 0; k < H; k++) acc += sN1[j][H + k] * mg[k];
        u[j] = silu_f(acc);
    }

    float hn[H];
#pragma unroll
    for (int j = 0; j < H; j++) {
        float acc = nb2[j];
#pragma unroll
        for (int k = 0; k < H; k++) acc += sN2[j][k] * u[k];
        hn[j] = hv[j] + acc;
    }
#pragma unroll
    for (int q = 0; q < 8; q++)
        hp[q] = make_float4(hn[4 * q], hn[4 * q + 1], hn[4 * q + 2], hn[4 * q + 3]);

    if (eW1n) {
        float Av[H], Bv[H];
#pragma unroll
        for (int j = 0; j < H; j++) {
            float accA = eb1n[j];
            float accB = 0.0f;
#pragma unroll
            for (int k = 0; k < H; k++) {
                accA += sEA[j][k] * hn[k];
                accB += sEB[j][k] * hn[k];
            }
            Av[j] = accA;
            Bv[j] = accB;
        }
        float4* Ao = (float4*)&g_A[i * H];
        float4* Bo = (float4*)&g_B[i * H];
#pragma unroll
        for (int q = 0; q < 8; q++) {
            Ao[q] = make_float4(Av[4 * q], Av[4 * q + 1], Av[4 * q + 2], Av[4 * q + 3]);
            Bo[q] = make_float4(Bv[4 * q], Bv[4 * q + 1], Bv[4 * q + 2], Bv[4 * q + 3]);
        }
    }

    if (linW) {
#pragma unroll
        for (int c = 0; c < 3; c++) {
            float acc = 0.0f;
#pragma unroll
            for (int k = 0; k < DX; k++) acc += linW[c * DX + k] * xv[k];
            out[i * 3 + c] = acc;
        }
    }
}

// ---------------------------------------------------------------------------
// launch
// ---------------------------------------------------------------------------
extern "C" void kernel_launch(void* const* d_in, const int* in_sizes, int n_in,
                              void* d_out, int out_size)
{
    const float* node_attrs = (const float*)d_in[0];
    const float* positions  = (const float*)d_in[1];
    const int*   edge_index = (const int*)  d_in[2];
    const float* proj_W     = (const float*)d_in[3];
    const float* emb_in_W   = (const float*)d_in[4];
    const float* emb_in_b   = (const float*)d_in[5];
    const float* edge_W1    = (const float*)d_in[6];   // [2][32][68]
    const float* edge_b1    = (const float*)d_in[7];   // [2][32]
    const float* edge_W2    = (const float*)d_in[8];   // [2][32][32]
    const float* edge_b2    = (const float*)d_in[9];   // [2][32]
    const float* node_W1    = (const float*)d_in[10];  // [2][32][64]
    const float* node_b1    = (const float*)d_in[11];  // [2][32]
    const float* node_W2    = (const float*)d_in[12];  // [2][32][32]
    const float* node_b2    = (const float*)d_in[13];  // [2][32]
    const float* coord_W1   = (const float*)d_in[14];  // [2][32][32]
    const float* coord_b1   = (const float*)d_in[15];  // [2][32]
    const float* coord_W2   = (const float*)d_in[16];  // [2][1][32]
    // d_in[17] emb_out_W, d_in[18] emb_out_b : dead in reference output
    const float* lin_W      = (const float*)d_in[19];  // [3][16]

    int n = in_sizes[0] / 3;
    int E = in_sizes[2] / 2;

    float* out = (float*)d_out;

    init_kernel<<<(n + 127) / 128, 128>>>(node_attrs, positions, proj_W,
                                          emb_in_W, emb_in_b,
                                          edge_W1, edge_b1, n);
    count_kernel<<<(E + 255) / 256, 256>>>(edge_index, E);

    for (int l = 0; l < 2; l++) {
        edge_kernel<<<(E + ETPB - 1) / ETPB, ETPB>>>(
            edge_index, E, positions,
            edge_W1 + l * H * 68,
            edge_W2 + l * H * H, edge_b2 + l * H,
            coord_W1 + l * H * H, coord_b1 + l * H,
            coord_W2 + l * H);

        node_kernel<<<(n + NTPB - 1) / NTPB, NTPB>>>(
            node_W1 + l * H * 2 * H, node_b1 + l * H,
            node_W2 + l * H * H,     node_b2 + l * H,
            (l == 0) ? edge_W1 + H * 68 : nullptr,
            (l == 0) ? edge_b1 + H      : nullptr,
            (l == 1) ? lin_W            : nullptr,
            out, n);
    }
}